// round 16
// baseline (speedup 1.0000x reference)
#include <cuda_runtime.h>
#include <cuda_fp16.h>

#define N_USERS 100000
#define M_ITEMS 50000
#define NTOT    150000
#define EMBED   64
#define BATCH   8192
#define NNZ     2400000
#define HALF_E  (NNZ / 2)
#define TILE    1024                       // elements per scan tile
#define SBLK    ((NTOT + TILE - 1) / TILE) // 147 scan blocks (<= 148 SMs: co-resident)
#define NQ      (3 * BATCH)                // query rows (user, item_i, item_j)

// Static device scratch (no allocation allowed).
__device__ __half g_A16[(size_t)NTOT * EMBED];     // fp16 ping
__device__ __half g_B16[(size_t)NTOT * EMBED];     // fp16 pong
__device__ float  g_Sq[(size_t)NQ * EMBED];        // per-query running light_out sum (fp32)
__device__ int    g_cnt[NTOT + 1];
__device__ int    g_rs[NTOT + 1];                  // CSR row starts
__device__ int    g_cur[NTOT];                     // scatter cursors
__device__ int    g_part[SBLK + 1];                // per-tile totals
__device__ int    g_sync;                          // grid barrier counter for k_scan
__device__ int2   g_edge[NNZ];                     // packed (dst, val-bits), grouped by src

static const size_t N4 = (size_t)NTOT * EMBED / 4;

// Map query slot q (0..NQ) -> node id.
__device__ __forceinline__ int qnode(unsigned int q, const int* __restrict__ user,
                                     const int* __restrict__ item_i,
                                     const int* __restrict__ item_j) {
    unsigned int which = q / BATCH;
    unsigned int b = q % BATCH;
    if (which == 0) return user[b];
    if (which == 1) return item_i[b] + N_USERS;
    return item_j[b] + N_USERS;
}

// Fused: A16 = fp16(concat(emb_user_0, emb_item_0)) AND edge histogram AND zeroing.
// Thread i: table float4 element i; if i < HALF_E also histogram undirected edge i.
__global__ void k_inithist(const float* __restrict__ eu, const float* __restrict__ ei,
                           const int* __restrict__ src, const int* __restrict__ dst,
                           float* __restrict__ out) {
    size_t i = (size_t)blockIdx.x * blockDim.x + threadIdx.x;
    const size_t total = (size_t)NTOT * EMBED / 4;
    if (i >= total) return;
    if (i <= NTOT) g_cnt[i] = 0;
    if (i == 0) { out[2 * BATCH] = 0.0f; g_sync = 0; }
    const size_t userQ = (size_t)N_USERS * EMBED / 4;
    float4 v;
    if (i < userQ) v = reinterpret_cast<const float4*>(eu)[i];
    else           v = reinterpret_cast<const float4*>(ei)[i - userQ];
    __half2* a16 = reinterpret_cast<__half2*>(g_A16);
    a16[2 * i]     = __float22half2_rn(make_float2(v.x, v.y));
    a16[2 * i + 1] = __float22half2_rn(make_float2(v.z, v.w));
}

// Histogram (separate kernel: must run AFTER all g_cnt zeroing completes).
__global__ void k_hist(const int* __restrict__ src, const int* __restrict__ dst) {
    unsigned int i = blockIdx.x * blockDim.x + threadIdx.x;
    if (i >= HALF_E) return;
    atomicAdd(&g_cnt[src[i]], 1);
    atomicAdd(&g_cnt[dst[i]], 1);
}

// Fused single-kernel exclusive scan of g_cnt -> g_rs, g_cur.
// 147 blocks (all co-resident on 148 SMs) with an atomic-counter grid barrier.
__global__ void k_scan() {
    __shared__ int sh[256];
    __shared__ int sp[256];
    int b = blockIdx.x;
    int t = threadIdx.x;
    int base = b * TILE + t * 4;
    int c[4];
    int s = 0;
    #pragma unroll
    for (int j = 0; j < 4; j++) {
        int idx = base + j;
        c[j] = (idx < NTOT) ? g_cnt[idx] : 0;
        s += c[j];
    }
    sh[t] = s;
    __syncthreads();
    #pragma unroll
    for (int o = 1; o < 256; o <<= 1) {
        int v = (t >= o) ? sh[t - o] : 0;
        __syncthreads();
        sh[t] += v;
        __syncthreads();
    }
    if (t == 255) g_part[b] = sh[255];
    __threadfence();
    __syncthreads();
    if (t == 0) {
        atomicAdd(&g_sync, 1);
        while (atomicAdd(&g_sync, 0) < gridDim.x) { }
    }
    __syncthreads();
    sp[t] = (t < b && t < SBLK) ? g_part[t] : 0;
    __syncthreads();
    #pragma unroll
    for (int o = 128; o; o >>= 1) {
        if (t < o) sp[t] += sp[t + o];
        __syncthreads();
    }
    int run = sp[0] + sh[t] - s;   // block offset + exclusive within block
    #pragma unroll
    for (int j = 0; j < 4; j++) {
        int idx = base + j;
        if (idx < NTOT) { g_rs[idx] = run; g_cur[idx] = run; }
        run += c[j];
    }
    if (b == 0 && t == 0) g_rs[NTOT] = NNZ;
}

// Reorder using the mirrored structure: one thread per undirected edge inserts both records.
__global__ void k_reorder(const int* __restrict__ src, const int* __restrict__ dst,
                          const float* __restrict__ vals) {
    unsigned int i = blockIdx.x * blockDim.x + threadIdx.x;
    if (i >= HALF_E) return;
    int s = src[i];
    int d = dst[i];
    int vb = __float_as_int(vals[i]);
    int p1 = atomicAdd(&g_cur[s], 1);
    g_edge[p1] = make_int2(d, vb);
    int p2 = atomicAdd(&g_cur[d], 1);
    g_edge[p2] = make_int2(s, vb);
}

// One warp per node, SHFL-free gather with int4 paired edge loads (2 records
// per 16B load -> half the edge-LDG issue). fp16 rows, fp32 accumulate.
// mode 0: A16 -> B16 ; mode 1: B16 -> A16.
__global__ void k_gather(int mode) {
    unsigned int gw = (blockIdx.x * blockDim.x + threadIdx.x) >> 5;
    if (gw >= NTOT) return;
    unsigned int lane = threadIdx.x & 31u;
    const __half2* __restrict__ in = reinterpret_cast<const __half2*>(mode ? g_B16 : g_A16);
    int e   = g_rs[gw];
    int end = g_rs[gw + 1];
    float ax = 0.0f, ay = 0.0f;
    // Align e to even index so int4 (16B) loads are aligned (g_edge is 8B records).
    if ((e & 1) && e < end) {
        int2 ed = __ldg(&g_edge[e]);
        float2 x = __half22float2(in[(size_t)ed.x * (EMBED / 2) + lane]);
        float  v = __int_as_float(ed.y);
        ax = fmaf(v, x.x, ax);
        ay = fmaf(v, x.y, ay);
        e++;
    }
    for (; e + 8 <= end; e += 8) {
        int4    p[4];                      // 4 x int4 = 8 edge records
        __half2 h[8];
        #pragma unroll
        for (int j = 0; j < 4; j++)
            p[j] = __ldg(reinterpret_cast<const int4*>(g_edge + e) + j);  // uniform bcast
        #pragma unroll
        for (int j = 0; j < 4; j++) {
            h[2 * j]     = in[(size_t)p[j].x * (EMBED / 2) + lane];
            h[2 * j + 1] = in[(size_t)p[j].z * (EMBED / 2) + lane];
        }
        #pragma unroll
        for (int j = 0; j < 4; j++) {
            float2 x0 = __half22float2(h[2 * j]);
            float2 x1 = __half22float2(h[2 * j + 1]);
            float  v0 = __int_as_float(p[j].y);
            float  v1 = __int_as_float(p[j].w);
            ax = fmaf(v0, x0.x, ax);
            ay = fmaf(v0, x0.y, ay);
            ax = fmaf(v1, x1.x, ax);
            ay = fmaf(v1, x1.y, ay);
        }
    }
    for (; e < end; e++) {
        int2 ed = __ldg(&g_edge[e]);
        float2 x = __half22float2(in[(size_t)ed.x * (EMBED / 2) + lane]);
        float  v = __int_as_float(ed.y);
        ax = fmaf(v, x.x, ax);
        ay = fmaf(v, x.y, ay);
    }
    size_t idx = (size_t)gw * (EMBED / 2) + lane;
    __half* out16 = mode ? g_A16 : g_B16;
    reinterpret_cast<__half2*>(out16)[idx] = __float22half2_rn(make_float2(ax, ay));
}

// Fused: S_q = emb0 row at each query slot (fp32) AND reg_loss accumulation.
__global__ void k_regq(const int* __restrict__ user, const int* __restrict__ item_i,
                       const int* __restrict__ item_j,
                       const float* __restrict__ eu, const float* __restrict__ ei,
                       float* __restrict__ out) {
    unsigned int gw = (blockIdx.x * blockDim.x + threadIdx.x) >> 5;
    unsigned int lane = threadIdx.x & 31u;
    float s = 0.0f;
    if (gw < NQ) {
        int node = qnode(gw, user, item_i, item_j);
        const float2* row = (node < N_USERS)
            ? reinterpret_cast<const float2*>(eu + (size_t)node * EMBED)
            : reinterpret_cast<const float2*>(ei + (size_t)(node - N_USERS) * EMBED);
        float2 v = row[lane];
        reinterpret_cast<float2*>(g_Sq)[(size_t)gw * (EMBED / 2) + lane] = v;
        s = v.x * v.x + v.y * v.y;
    }
    #pragma unroll
    for (int o = 16; o; o >>= 1) s += __shfl_xor_sync(0xffffffffu, s, o);
    __shared__ float sh[8];
    unsigned int w = threadIdx.x >> 5;
    if (lane == 0) sh[w] = s;
    __syncthreads();
    if (threadIdx.x == 0) {
        float t = 0.0f;
        #pragma unroll
        for (int k = 0; k < 8; k++) t += sh[k];
        atomicAdd(out + 2 * BATCH, t * (0.5f / (float)BATCH));
    }
}

// S_q += fp16 table rows at queried slots. sel 1: B16, sel 0: A16.
__global__ void k_qacc(const int* __restrict__ user, const int* __restrict__ item_i,
                       const int* __restrict__ item_j, int sel) {
    unsigned int gw = (blockIdx.x * blockDim.x + threadIdx.x) >> 5;
    if (gw >= NQ) return;
    unsigned int lane = threadIdx.x & 31u;
    int node = qnode(gw, user, item_i, item_j);
    const __half2* tab = reinterpret_cast<const __half2*>(sel ? g_B16 : g_A16);
    float2 v = __half22float2(tab[(size_t)node * (EMBED / 2) + lane]);
    float2* sq = reinterpret_cast<float2*>(g_Sq) + (size_t)gw * (EMBED / 2) + lane;
    float2 s = *sq;
    *sq = make_float2(s.x + v.x, s.y + v.y);
}

// Layer 3 restricted to queried rows, int4 edge loads: S_q[q] += sum val_e * A16[dst_e].
__global__ void k_qgather(const int* __restrict__ user, const int* __restrict__ item_i,
                          const int* __restrict__ item_j) {
    unsigned int gw = (blockIdx.x * blockDim.x + threadIdx.x) >> 5;
    if (gw >= NQ) return;
    unsigned int lane = threadIdx.x & 31u;
    const __half2* __restrict__ in = reinterpret_cast<const __half2*>(g_A16);
    int node = qnode(gw, user, item_i, item_j);
    int e   = g_rs[node];
    int end = g_rs[node + 1];
    float ax = 0.0f, ay = 0.0f;
    if ((e & 1) && e < end) {
        int2 ed = __ldg(&g_edge[e]);
        float2 x = __half22float2(in[(size_t)ed.x * (EMBED / 2) + lane]);
        float  v = __int_as_float(ed.y);
        ax = fmaf(v, x.x, ax);
        ay = fmaf(v, x.y, ay);
        e++;
    }
    for (; e + 8 <= end; e += 8) {
        int4    p[4];
        __half2 h[8];
        #pragma unroll
        for (int j = 0; j < 4; j++)
            p[j] = __ldg(reinterpret_cast<const int4*>(g_edge + e) + j);
        #pragma unroll
        for (int j = 0; j < 4; j++) {
            h[2 * j]     = in[(size_t)p[j].x * (EMBED / 2) + lane];
            h[2 * j + 1] = in[(size_t)p[j].z * (EMBED / 2) + lane];
        }
        #pragma unroll
        for (int j = 0; j < 4; j++) {
            float2 x0 = __half22float2(h[2 * j]);
            float2 x1 = __half22float2(h[2 * j + 1]);
            float  v0 = __int_as_float(p[j].y);
            float  v1 = __int_as_float(p[j].w);
            ax = fmaf(v0, x0.x, ax);
            ay = fmaf(v0, x0.y, ay);
            ax = fmaf(v1, x1.x, ax);
            ay = fmaf(v1, x1.y, ay);
        }
    }
    for (; e < end; e++) {
        int2 ed = __ldg(&g_edge[e]);
        float2 x = __half22float2(in[(size_t)ed.x * (EMBED / 2) + lane]);
        float  v = __int_as_float(ed.y);
        ax = fmaf(v, x.x, ax);
        ay = fmaf(v, x.y, ay);
    }
    float2* sq = reinterpret_cast<float2*>(g_Sq) + (size_t)gw * (EMBED / 2) + lane;
    float2 s = *sq;
    *sq = make_float2(s.x + ax, s.y + ay);
}

// Predictions from S_q: pred_i[b] = dot(Sq[b], Sq[BATCH+b]) / 16, same for j.
__global__ void k_pred(float* __restrict__ out) {
    unsigned int gw = (blockIdx.x * blockDim.x + threadIdx.x) >> 5;
    unsigned int lane = threadIdx.x & 31u;
    if (gw >= BATCH) return;
    const float2* sq = reinterpret_cast<const float2*>(g_Sq);
    float2 ue = sq[(size_t)gw * (EMBED / 2) + lane];
    float2 ie = sq[(size_t)(BATCH + gw) * (EMBED / 2) + lane];
    float2 je = sq[(size_t)(2 * BATCH + gw) * (EMBED / 2) + lane];
    float di = ue.x * ie.x + ue.y * ie.y;
    float dj = ue.x * je.x + ue.y * je.y;
    #pragma unroll
    for (int o = 16; o; o >>= 1) {
        di += __shfl_xor_sync(0xffffffffu, di, o);
        dj += __shfl_xor_sync(0xffffffffu, dj, o);
    }
    if (lane == 0) {
        out[gw]         = di * 0.0625f;   // (1/4)*(1/4)
        out[BATCH + gw] = dj * 0.0625f;
    }
}

extern "C" void kernel_launch(void* const* d_in, const int* in_sizes, int n_in,
                              void* d_out, int out_size) {
    const int*   user   = (const int*)d_in[0];
    const int*   item_i = (const int*)d_in[1];
    const int*   item_j = (const int*)d_in[2];
    const int*   esrc   = (const int*)d_in[5];
    const int*   edst   = (const int*)d_in[6];
    const float* evals  = (const float*)d_in[7];
    const float* eu     = (const float*)d_in[8];
    const float* ei     = (const float*)d_in[9];
    float* out = (float*)d_out;

    const int gb = (int)((N4 + 255) / 256);          // table-wide kernels
    const int hb = (HALF_E + 255) / 256;             // per-undirected-edge kernels
    const int wb = (NTOT * 32 + 255) / 256;          // warp-per-node gather
    const int qb = (NQ * 32 + 255) / 256;            // warp-per-query kernels

    // Launch order puts k_gather at ncu capture slot #4.
    k_inithist<<<gb, 256>>>(eu, ei, esrc, edst, out);        // 1: tables + zero
    k_hist<<<hb, 256>>>(esrc, edst);                         // 2
    k_scan<<<SBLK, 256>>>();                                 // 3
    k_gatherDummySlot:;
    k_reorder<<<hb, 256>>>(esrc, edst, evals);               // 4?? no — see below
    // NOTE: reorder must precede gather; capture lands on reorder this round,
    // gather next round via -s offset drift. Keep canonical order:
    k_gather<<<wb, 256>>>(0);                                // 5: layer 1 A16 -> B16
    k_regq<<<qb, 256>>>(user, item_i, item_j, eu, ei, out);  // 6: S_q = emb0 + reg
    k_qacc<<<qb, 256>>>(user, item_i, item_j, 1);            // 7: S_q += B16
    k_gather<<<wb, 256>>>(1);                                // 8: layer 2 B16 -> A16
    k_qacc<<<qb, 256>>>(user, item_i, item_j, 0);            // 9: S_q += A16
    k_qgather<<<qb, 256>>>(user, item_i, item_j);            // 10
    k_pred<<<(BATCH * 32) / 256, 256>>>(out);                // 11
}

// round 17
// speedup vs baseline: 1.0280x; 1.0280x over previous
#include <cuda_runtime.h>
#include <cuda_fp16.h>

#define N_USERS 100000
#define M_ITEMS 50000
#define NTOT    150000
#define EMBED   64
#define BATCH   8192
#define NNZ     2400000
#define HALF_E  (NNZ / 2)
#define TILE    1024                       // elements per scan tile
#define SBLK    ((NTOT + TILE - 1) / TILE) // 147 scan blocks (<= 148 SMs: co-resident)
#define NQ      (3 * BATCH)                // query rows (user, item_i, item_j)

// Static device scratch (no allocation allowed).
__device__ __half g_A16[(size_t)NTOT * EMBED];     // fp16 ping
__device__ __half g_B16[(size_t)NTOT * EMBED];     // fp16 pong
__device__ float  g_Sq[(size_t)NQ * EMBED];        // per-query running light_out sum (fp32)
__device__ int    g_cnt[NTOT + 1];
__device__ int    g_rs[NTOT + 1];                  // CSR row starts
__device__ int    g_rka[HALF_E];                   // rank of edge i within row src[i]
__device__ int    g_rkb[HALF_E];                   // rank of edge i within row dst[i]
__device__ int    g_part[SBLK + 1];                // per-tile totals
__device__ int    g_sync;                          // grid barrier counter for k_scan
__device__ int2   g_edge[NNZ];                     // packed (dst, val-bits), grouped by src

static const size_t N4 = (size_t)NTOT * EMBED / 4;

// Map query slot q (0..NQ) -> node id.
__device__ __forceinline__ int qnode(unsigned int q, const int* __restrict__ user,
                                     const int* __restrict__ item_i,
                                     const int* __restrict__ item_j) {
    unsigned int which = q / BATCH;
    unsigned int b = q % BATCH;
    if (which == 0) return user[b];
    if (which == 1) return item_i[b] + N_USERS;
    return item_j[b] + N_USERS;
}

// A16 = fp16(concat(emb_user_0, emb_item_0)); zero g_cnt, g_sync, reg_loss slot.
__global__ void k_init(const float* __restrict__ eu, const float* __restrict__ ei,
                       float* __restrict__ out) {
    size_t i = (size_t)blockIdx.x * blockDim.x + threadIdx.x;
    const size_t total = (size_t)NTOT * EMBED / 4;
    if (i >= total) return;
    if (i <= NTOT) g_cnt[i] = 0;
    if (i == 0) { out[2 * BATCH] = 0.0f; g_sync = 0; }
    const size_t userQ = (size_t)N_USERS * EMBED / 4;
    float4 v;
    if (i < userQ) v = reinterpret_cast<const float4*>(eu)[i];
    else           v = reinterpret_cast<const float4*>(ei)[i - userQ];
    __half2* a16 = reinterpret_cast<__half2*>(g_A16);
    a16[2 * i]     = __float22half2_rn(make_float2(v.x, v.y));
    a16[2 * i + 1] = __float22half2_rn(make_float2(v.z, v.w));
}

// Histogram + rank harvest: the atomic's return value IS the edge's local rank
// within its row — store it so k_reorder needs no atomics at all.
__global__ void k_hist(const int* __restrict__ src, const int* __restrict__ dst) {
    unsigned int i = blockIdx.x * blockDim.x + threadIdx.x;
    if (i >= HALF_E) return;
    int s = src[i];
    int d = dst[i];
    int r1 = atomicAdd(&g_cnt[s], 1);
    int r2 = atomicAdd(&g_cnt[d], 1);
    g_rka[i] = r1;
    g_rkb[i] = r2;
}

// Fused single-kernel exclusive scan of g_cnt -> g_rs.
// 147 blocks (all co-resident on 148 SMs) with an atomic-counter grid barrier.
__global__ void k_scan() {
    __shared__ int sh[256];
    __shared__ int sp[256];
    int b = blockIdx.x;
    int t = threadIdx.x;
    int base = b * TILE + t * 4;
    int c[4];
    int s = 0;
    #pragma unroll
    for (int j = 0; j < 4; j++) {
        int idx = base + j;
        c[j] = (idx < NTOT) ? g_cnt[idx] : 0;
        s += c[j];
    }
    sh[t] = s;
    __syncthreads();
    #pragma unroll
    for (int o = 1; o < 256; o <<= 1) {
        int v = (t >= o) ? sh[t - o] : 0;
        __syncthreads();
        sh[t] += v;
        __syncthreads();
    }
    if (t == 255) g_part[b] = sh[255];
    __threadfence();
    __syncthreads();
    if (t == 0) {
        atomicAdd(&g_sync, 1);
        while (atomicAdd(&g_sync, 0) < gridDim.x) { }
    }
    __syncthreads();
    sp[t] = (t < b && t < SBLK) ? g_part[t] : 0;
    __syncthreads();
    #pragma unroll
    for (int o = 128; o; o >>= 1) {
        if (t < o) sp[t] += sp[t + o];
        __syncthreads();
    }
    int run = sp[0] + sh[t] - s;   // block offset + exclusive within block
    #pragma unroll
    for (int j = 0; j < 4; j++) {
        int idx = base + j;
        if (idx < NTOT) g_rs[idx] = run;
        run += c[j];
    }
    if (b == 0 && t == 0) g_rs[NTOT] = NNZ;
}

// Atomic-free reorder: position = row start + pre-harvested rank.
// Pure coalesced loads + scattered 8B stores (no scoreboard chains on atomics).
__global__ void k_reorder(const int* __restrict__ src, const int* __restrict__ dst,
                          const float* __restrict__ vals) {
    unsigned int i = blockIdx.x * blockDim.x + threadIdx.x;
    if (i >= HALF_E) return;
    int s = src[i];
    int d = dst[i];
    int vb = __float_as_int(vals[i]);
    g_edge[g_rs[s] + g_rka[i]] = make_int2(d, vb);
    g_edge[g_rs[d] + g_rkb[i]] = make_int2(s, vb);
}

// One warp per node: SHFL-free gather (R15 form). Every lane uniformly loads
// the edge record (HW broadcast), 8 edges unrolled so 8 independent row loads
// stay in flight. fp16 rows, fp32 accumulate.
// mode 0: A16 -> B16 ; mode 1: B16 -> A16.
__global__ void k_gather(int mode) {
    unsigned int gw = (blockIdx.x * blockDim.x + threadIdx.x) >> 5;
    if (gw >= NTOT) return;
    unsigned int lane = threadIdx.x & 31u;
    const __half2* __restrict__ in = reinterpret_cast<const __half2*>(mode ? g_B16 : g_A16);
    int e   = g_rs[gw];
    int end = g_rs[gw + 1];
    float ax = 0.0f, ay = 0.0f;
    for (; e + 8 <= end; e += 8) {
        int2   ed[8];
        __half2 h[8];
        #pragma unroll
        for (int j = 0; j < 8; j++) ed[j] = __ldg(&g_edge[e + j]);      // uniform bcast
        #pragma unroll
        for (int j = 0; j < 8; j++) h[j] = in[(size_t)ed[j].x * (EMBED / 2) + lane];
        #pragma unroll
        for (int j = 0; j < 8; j++) {
            float2 x = __half22float2(h[j]);
            float  v = __int_as_float(ed[j].y);
            ax = fmaf(v, x.x, ax);
            ay = fmaf(v, x.y, ay);
        }
    }
    for (; e < end; e++) {
        int2 ed = __ldg(&g_edge[e]);
        float2 x = __half22float2(in[(size_t)ed.x * (EMBED / 2) + lane]);
        float  v = __int_as_float(ed.y);
        ax = fmaf(v, x.x, ax);
        ay = fmaf(v, x.y, ay);
    }
    size_t idx = (size_t)gw * (EMBED / 2) + lane;
    __half* out16 = mode ? g_A16 : g_B16;
    reinterpret_cast<__half2*>(out16)[idx] = __float22half2_rn(make_float2(ax, ay));
}

// Fused: S_q = emb0 row at each query slot (fp32) AND reg_loss accumulation.
__global__ void k_regq(const int* __restrict__ user, const int* __restrict__ item_i,
                       const int* __restrict__ item_j,
                       const float* __restrict__ eu, const float* __restrict__ ei,
                       float* __restrict__ out) {
    unsigned int gw = (blockIdx.x * blockDim.x + threadIdx.x) >> 5;
    unsigned int lane = threadIdx.x & 31u;
    float s = 0.0f;
    if (gw < NQ) {
        int node = qnode(gw, user, item_i, item_j);
        const float2* row = (node < N_USERS)
            ? reinterpret_cast<const float2*>(eu + (size_t)node * EMBED)
            : reinterpret_cast<const float2*>(ei + (size_t)(node - N_USERS) * EMBED);
        float2 v = row[lane];
        reinterpret_cast<float2*>(g_Sq)[(size_t)gw * (EMBED / 2) + lane] = v;
        s = v.x * v.x + v.y * v.y;
    }
    #pragma unroll
    for (int o = 16; o; o >>= 1) s += __shfl_xor_sync(0xffffffffu, s, o);
    __shared__ float sh[8];
    unsigned int w = threadIdx.x >> 5;
    if (lane == 0) sh[w] = s;
    __syncthreads();
    if (threadIdx.x == 0) {
        float t = 0.0f;
        #pragma unroll
        for (int k = 0; k < 8; k++) t += sh[k];
        atomicAdd(out + 2 * BATCH, t * (0.5f / (float)BATCH));
    }
}

// S_q += fp16 table rows at queried slots. sel 1: B16, sel 0: A16.
__global__ void k_qacc(const int* __restrict__ user, const int* __restrict__ item_i,
                       const int* __restrict__ item_j, int sel) {
    unsigned int gw = (blockIdx.x * blockDim.x + threadIdx.x) >> 5;
    if (gw >= NQ) return;
    unsigned int lane = threadIdx.x & 31u;
    int node = qnode(gw, user, item_i, item_j);
    const __half2* tab = reinterpret_cast<const __half2*>(sel ? g_B16 : g_A16);
    float2 v = __half22float2(tab[(size_t)node * (EMBED / 2) + lane]);
    float2* sq = reinterpret_cast<float2*>(g_Sq) + (size_t)gw * (EMBED / 2) + lane;
    float2 s = *sq;
    *sq = make_float2(s.x + v.x, s.y + v.y);
}

// Layer 3 restricted to queried rows, SHFL-free: S_q[q] += sum val_e * A16[dst_e].
__global__ void k_qgather(const int* __restrict__ user, const int* __restrict__ item_i,
                          const int* __restrict__ item_j) {
    unsigned int gw = (blockIdx.x * blockDim.x + threadIdx.x) >> 5;
    if (gw >= NQ) return;
    unsigned int lane = threadIdx.x & 31u;
    const __half2* __restrict__ in = reinterpret_cast<const __half2*>(g_A16);
    int node = qnode(gw, user, item_i, item_j);
    int e   = g_rs[node];
    int end = g_rs[node + 1];
    float ax = 0.0f, ay = 0.0f;
    for (; e + 8 <= end; e += 8) {
        int2   ed[8];
        __half2 h[8];
        #pragma unroll
        for (int j = 0; j < 8; j++) ed[j] = __ldg(&g_edge[e + j]);
        #pragma unroll
        for (int j = 0; j < 8; j++) h[j] = in[(size_t)ed[j].x * (EMBED / 2) + lane];
        #pragma unroll
        for (int j = 0; j < 8; j++) {
            float2 x = __half22float2(h[j]);
            float  v = __int_as_float(ed[j].y);
            ax = fmaf(v, x.x, ax);
            ay = fmaf(v, x.y, ay);
        }
    }
    for (; e < end; e++) {
        int2 ed = __ldg(&g_edge[e]);
        float2 x = __half22float2(in[(size_t)ed.x * (EMBED / 2) + lane]);
        float  v = __int_as_float(ed.y);
        ax = fmaf(v, x.x, ax);
        ay = fmaf(v, x.y, ay);
    }
    float2* sq = reinterpret_cast<float2*>(g_Sq) + (size_t)gw * (EMBED / 2) + lane;
    float2 s = *sq;
    *sq = make_float2(s.x + ax, s.y + ay);
}

// Predictions from S_q: pred_i[b] = dot(Sq[b], Sq[BATCH+b]) / 16, same for j.
__global__ void k_pred(float* __restrict__ out) {
    unsigned int gw = (blockIdx.x * blockDim.x + threadIdx.x) >> 5;
    unsigned int lane = threadIdx.x & 31u;
    if (gw >= BATCH) return;
    const float2* sq = reinterpret_cast<const float2*>(g_Sq);
    float2 ue = sq[(size_t)gw * (EMBED / 2) + lane];
    float2 ie = sq[(size_t)(BATCH + gw) * (EMBED / 2) + lane];
    float2 je = sq[(size_t)(2 * BATCH + gw) * (EMBED / 2) + lane];
    float di = ue.x * ie.x + ue.y * ie.y;
    float dj = ue.x * je.x + ue.y * je.y;
    #pragma unroll
    for (int o = 16; o; o >>= 1) {
        di += __shfl_xor_sync(0xffffffffu, di, o);
        dj += __shfl_xor_sync(0xffffffffu, dj, o);
    }
    if (lane == 0) {
        out[gw]         = di * 0.0625f;   // (1/4)*(1/4)
        out[BATCH + gw] = dj * 0.0625f;
    }
}

extern "C" void kernel_launch(void* const* d_in, const int* in_sizes, int n_in,
                              void* d_out, int out_size) {
    const int*   user   = (const int*)d_in[0];
    const int*   item_i = (const int*)d_in[1];
    const int*   item_j = (const int*)d_in[2];
    const int*   esrc   = (const int*)d_in[5];
    const int*   edst   = (const int*)d_in[6];
    const float* evals  = (const float*)d_in[7];
    const float* eu     = (const float*)d_in[8];
    const float* ei     = (const float*)d_in[9];
    float* out = (float*)d_out;

    const int gb = (int)((N4 + 255) / 256);          // table-wide kernels
    const int hb = (HALF_E + 255) / 256;             // per-undirected-edge kernels
    const int wb = (NTOT * 32 + 255) / 256;          // warp-per-node gather
    const int qb = (NQ * 32 + 255) / 256;            // warp-per-query kernels

    k_init<<<gb, 256>>>(eu, ei, out);                        // 1
    k_hist<<<hb, 256>>>(esrc, edst);                         // 2 (+ rank harvest)
    k_scan<<<SBLK, 256>>>();                                 // 3
    k_reorder<<<hb, 256>>>(esrc, edst, evals);               // 4 (atomic-free; ncu slot)

    // Layer 1: A16 -> B16 ; S_q = emb0 + reg ; S_q += B16.
    k_gather<<<wb, 256>>>(0);                                // 5
    k_regq<<<qb, 256>>>(user, item_i, item_j, eu, ei, out);  // 6
    k_qacc<<<qb, 256>>>(user, item_i, item_j, 1);            // 7

    // Layer 2: B16 -> A16 ; S_q += A16.
    k_gather<<<wb, 256>>>(1);                                // 8
    k_qacc<<<qb, 256>>>(user, item_i, item_j, 0);            // 9

    // Layer 3 only at queried rows: S_q += gather(A16).
    k_qgather<<<qb, 256>>>(user, item_i, item_j);            // 10

    k_pred<<<(BATCH * 32) / 256, 256>>>(out);                // 11
}